// round 14
// baseline (speedup 1.0000x reference)
#include <cuda_runtime.h>
#include <cuda_bf16.h>
#include <cstdint>

// LoRA low-rank, 2-kernel pipeline (round 13 = R12 with XP bug fixed):
//   phase1 : tp[ks][m][r] = sum_{k in slice} x[m][k] * 2*A[r][k]
//            KC=32, occ 3, pitch-65 transpose (64 m per row + pad).
//   phase2 : out[m][o] = sum_r (sum_ks tp) * B[o][r] + bias[o]
//            2 o-cols/thread (bu = 32 regs), occ 3, grid 1024.

#define IN_F   4096
#define OUT_F  4096
#define RANK   16
#define M_TOT  8192

#define KSPLIT 8
#define KRANGE (IN_F / KSPLIT)    // 512
#define MT     64                 // m rows per phase-1 block
#define KC     32                 // k chunk staged in smem
#define NCH    (KRANGE / KC)      // 16
#define XP     65                 // xs pitch over m (64 rows + 1 pad)

#define OTPB   512                // o columns per phase-2 block
#define MSLAB  64                 // m rows per phase-2 block

__device__ __align__(16) float g_tp[KSPLIT][M_TOT][RANK];    // 4 MB partials

typedef unsigned long long u64;

__device__ __forceinline__ u64 pk2(float lo, float hi) {
    u64 r; asm("mov.b64 %0, {%1,%2};" : "=l"(r) : "f"(lo), "f"(hi)); return r;
}
__device__ __forceinline__ void fma2(u64 &d, u64 a, u64 b) {
    asm("fma.rn.f32x2 %0, %1, %2, %0;" : "+l"(d) : "l"(a), "l"(b));
}
__device__ __forceinline__ float2 up2(u64 v) {
    float2 f; asm("mov.b64 {%0,%1}, %2;" : "=f"(f.x), "=f"(f.y) : "l"(v)); return f;
}

// ---------------- phase 1 ----------------
// smem (32768 B):
//   [0     , 16640)  xs[2][KC][XP] floats   (x tiles, transposed over m)
//   [16640 , 20736)  as4[2][KC*4] float4    (A tiles, x2 folded)
//   [0     , 32768)  tredf[8][64][16] floats (reduction; aliases all)
__global__ __launch_bounds__(256, 3)
void lora_phase1(const float* __restrict__ x,
                 const float* __restrict__ A) {
    __shared__ __align__(16) char sraw[32768];
    float*  xs    = (float*)sraw;
    float4* as4   = (float4*)(sraw + 16640);
    float*  tredf = (float*)sraw;

    const int tid  = threadIdx.x;
    const int lane = tid & 31;
    const int w    = tid >> 5;                  // 8 warps
    const int ks   = blockIdx.x & (KSPLIT - 1);
    const int mt   = blockIdx.x >> 3;           // 0..127
    const int mbase = mt * MT;
    const int k0    = ks * KRANGE;

    // full-line LDG mapping: lanes 0..7 cover one whole 128B line of a row
    const int lm = tid >> 3;                    // 0..31 (row in 32-row group)
    const int lc = (tid & 7) * 4;               // col floats within 32-col chunk
    const float* xg = x + (size_t)(mbase + lm) * IN_F + k0 + lc;

    // A staging (threads 0..127): thread -> (k-in-chunk ka, rank-quad rq)
    const int ka = tid >> 2;                    // 0..31 (for tid<128)
    const int rq = tid & 3;                     // 0..3
    const float* Ag = A + (size_t)(4 * rq) * IN_F + k0 + ka;

    u64 acc[2][8];
    #pragma unroll
    for (int mp = 0; mp < 2; ++mp)
        #pragma unroll
        for (int rp = 0; rp < 8; ++rp) acc[mp][rp] = 0ull;

    float4 xr[2], ar;

    // prologue: chunk 0 (rows lm, lm+32)
    #pragma unroll
    for (int i = 0; i < 2; ++i)
        xr[i] = *(const float4*)(xg + (size_t)(32 * i) * IN_F);
    if (tid < 128) {
        ar.x = Ag[0];
        ar.y = Ag[(size_t)1 * IN_F];
        ar.z = Ag[(size_t)2 * IN_F];
        ar.w = Ag[(size_t)3 * IN_F];
    }

    #pragma unroll
    for (int i = 0; i < 2; ++i) {
        const int m = lm + 32 * i;
        xs[(lc + 0) * XP + m] = xr[i].x;
        xs[(lc + 1) * XP + m] = xr[i].y;
        xs[(lc + 2) * XP + m] = xr[i].z;
        xs[(lc + 3) * XP + m] = xr[i].w;
    }
    if (tid < 128)
        as4[tid] = make_float4(2.0f * ar.x, 2.0f * ar.y, 2.0f * ar.z, 2.0f * ar.w);
    __syncthreads();

    for (int c = 0; c < NCH; ++c) {
        const int buf = c & 1;

        if (c + 1 < NCH) {                      // prefetch chunk c+1
            const int kc1 = (c + 1) * KC;
            #pragma unroll
            for (int i = 0; i < 2; ++i)
                xr[i] = *(const float4*)(xg + kc1 + (size_t)(32 * i) * IN_F);
            if (tid < 128) {
                ar.x = Ag[kc1];
                ar.y = Ag[kc1 + (size_t)1 * IN_F];
                ar.z = Ag[kc1 + (size_t)2 * IN_F];
                ar.w = Ag[kc1 + (size_t)3 * IN_F];
            }
        }

        // compute: warp w covers k = w*4 .. w*4+3 of this chunk
        const float*  xbc = xs + buf * (KC * XP);
        const float4* abc = as4 + buf * (KC * 4);
        #pragma unroll
        for (int kk = 0; kk < 4; ++kk) {
            const int k = w * 4 + kk;
            const float xv0 = xbc[k * XP + lane];         // m = lane
            const float xv1 = xbc[k * XP + 32 + lane];    // m = lane + 32
            const u64 xd0 = pk2(xv0, xv0);
            const u64 xd1 = pk2(xv1, xv1);
            const ulonglong2* ap = (const ulonglong2*)(abc + k * 4);
            const ulonglong2 a01 = ap[0], a23 = ap[1];
            fma2(acc[0][0], xd0, a01.x); fma2(acc[1][0], xd1, a01.x);
            fma2(acc[0][1], xd0, a01.y); fma2(acc[1][1], xd1, a01.y);
            fma2(acc[0][2], xd0, a23.x); fma2(acc[1][2], xd1, a23.x);
            fma2(acc[0][3], xd0, a23.y); fma2(acc[1][3], xd1, a23.y);
            const ulonglong2 a45 = ap[2], a67 = ap[3];
            fma2(acc[0][4], xd0, a45.x); fma2(acc[1][4], xd1, a45.x);
            fma2(acc[0][5], xd0, a45.y); fma2(acc[1][5], xd1, a45.y);
            fma2(acc[0][6], xd0, a67.x); fma2(acc[1][6], xd1, a67.x);
            fma2(acc[0][7], xd0, a67.y); fma2(acc[1][7], xd1, a67.y);
        }

        if (c + 1 < NCH) {                      // stage chunk c+1
            float* xb = xs + ((c + 1) & 1) * (KC * XP);
            #pragma unroll
            for (int i = 0; i < 2; ++i) {
                const int m = lm + 32 * i;
                xb[(lc + 0) * XP + m] = xr[i].x;
                xb[(lc + 1) * XP + m] = xr[i].y;
                xb[(lc + 2) * XP + m] = xr[i].z;
                xb[(lc + 3) * XP + m] = xr[i].w;
            }
            if (tid < 128)
                as4[((c + 1) & 1) * (KC * 4) + tid] =
                    make_float4(2.0f * ar.x, 2.0f * ar.y, 2.0f * ar.z, 2.0f * ar.w);
        }
        __syncthreads();
    }

    // ---- cross-warp reduction (tredf aliases all smem; lane-swizzled) ----
    #pragma unroll
    for (int mp = 0; mp < 2; ++mp) {
        const int m = lane + 32 * mp;
        const int base = w * 1024 + m * 16;
        #pragma unroll
        for (int rp = 0; rp < 8; ++rp) {
            const float2 f = up2(acc[mp][rp]);
            tredf[base + ((2 * rp     + lane) & 15)] = f.x;
            tredf[base + ((2 * rp + 1 + lane) & 15)] = f.y;
        }
    }
    __syncthreads();

    {   // final sum: thread -> (m = tid>>2, rank quad r0)
        const int m  = tid >> 2;
        const int r0 = (tid & 3) * 4;
        const int lw = m & 31;                  // writer's lane for this m
        float s[4];
        #pragma unroll
        for (int j = 0; j < 4; ++j) {
            const int cr = (r0 + j + lw) & 15;
            float v = 0.0f;
            #pragma unroll
            for (int w8 = 0; w8 < 8; ++w8)
                v += tredf[w8 * 1024 + m * 16 + cr];
            s[j] = v;
        }
        *(float4*)&g_tp[ks][mbase + m][r0] = make_float4(s[0], s[1], s[2], s[3]);
    }
}

// ---------------- phase 2 ----------------
// 2 o-columns per thread -> bu = 32 regs -> occupancy 3.
__global__ __launch_bounds__(256, 3)
void lora_phase2(const float* __restrict__ B,
                 const float* __restrict__ bias,
                 float* __restrict__ out) {
    __shared__ u64 t_d[MSLAB][RANK];     // 8 KB, (t,t) duplicated

    const int tid   = threadIdx.x;
    const int oblk  = blockIdx.x & 7;            // 8 o-blocks of 512
    const int mslab = blockIdx.x >> 3;           // 128 m-slabs of 64
    const int o0    = oblk * OTPB + tid * 2;
    const int m0    = mslab * MSLAB;

    // load 2 B rows once, pack o-pairs
    u64 bu[RANK];
    {
        float B0[RANK], B1[RANK];
        #pragma unroll
        for (int q = 0; q < 4; ++q) {
            *(float4*)&B0[4 * q] = *(const float4*)&B[(size_t)(o0)     * RANK + 4 * q];
            *(float4*)&B1[4 * q] = *(const float4*)&B[(size_t)(o0 + 1) * RANK + 4 * q];
        }
        #pragma unroll
        for (int r = 0; r < RANK; ++r)
            bu[r] = pk2(B0[r], B1[r]);
    }
    const float2 bi2 = *(const float2*)&bias[o0];
    const u64 bias2 = pk2(bi2.x, bi2.y);

    // stage t slab: sum KSPLIT partials, store duplicated
    {
        const int m = tid >> 2, q = tid & 3;     // 256 threads -> 64m x 4 quads
        float4 s = make_float4(0, 0, 0, 0);
        #pragma unroll
        for (int sl = 0; sl < KSPLIT; ++sl) {
            const float4 v = *(const float4*)&g_tp[sl][m0 + m][4 * q];
            s.x += v.x; s.y += v.y; s.z += v.z; s.w += v.w;
        }
        t_d[m][4 * q + 0] = pk2(s.x, s.x);
        t_d[m][4 * q + 1] = pk2(s.y, s.y);
        t_d[m][4 * q + 2] = pk2(s.z, s.z);
        t_d[m][4 * q + 3] = pk2(s.w, s.w);
    }
    __syncthreads();

    // main loop: 2 m per iteration -> 2 independent FMA chains
    for (int m = 0; m < MSLAB; m += 2) {
        const ulonglong2* tp0 = (const ulonglong2*)&t_d[m][0];
        const ulonglong2* tp1 = (const ulonglong2*)&t_d[m + 1][0];
        u64 a0 = bias2, b0 = bias2;
        #pragma unroll
        for (int rp = 0; rp < 8; ++rp) {
            const ulonglong2 t20 = tp0[rp];
            const ulonglong2 t21 = tp1[rp];
            fma2(a0, t20.x, bu[2 * rp]);
            fma2(b0, t21.x, bu[2 * rp]);
            fma2(a0, t20.y, bu[2 * rp + 1]);
            fma2(b0, t21.y, bu[2 * rp + 1]);
        }
        const float2 fa = up2(a0), fb = up2(b0);
        *(float2*)&out[(size_t)(m0 + m)     * OUT_F + o0] = fa;
        *(float2*)&out[(size_t)(m0 + m + 1) * OUT_F + o0] = fb;
    }
}

extern "C" void kernel_launch(void* const* d_in, const int* in_sizes, int n_in,
                              void* d_out, int out_size) {
    const float* x    = (const float*)d_in[0];   // [8192, 4096]
    const float* A    = (const float*)d_in[1];   // [16, 4096]
    const float* B    = (const float*)d_in[2];   // [4096, 16]
    const float* bias = (const float*)d_in[3];   // [4096]
    float* out = (float*)d_out;                  // [8192, 4096]

    lora_phase1<<<(M_TOT / MT) * KSPLIT, 256>>>(x, A);
    lora_phase2<<<(OUT_F / OTPB) * (M_TOT / MSLAB), 256>>>(B, bias, out);
}

// round 15
// speedup vs baseline: 1.2389x; 1.2389x over previous
#include <cuda_runtime.h>
#include <cuda_bf16.h>
#include <cstdint>

// LoRA low-rank, fused producer/consumer pipeline (round 14):
//   zero   : reset per-tile counters (graph replay safe)
//   fused  : blocks 0..1023   = phase1 (R10 verbatim) + release flag
//            blocks 1024..2047 = phase2 (R10 shape, MSLAB=32) after acquire spin
// Overlaps phase2 with phase1's tail instead of a global kernel barrier.

#define IN_F   4096
#define OUT_F  4096
#define RANK   16
#define M_TOT  8192

#define KSPLIT 8
#define KRANGE (IN_F / KSPLIT)    // 512
#define MT     64                 // m rows per phase-1 block
#define KC     64                 // k chunk staged in smem
#define NCH    (KRANGE / KC)      // 8
#define XP     65                 // xs pitch over m (64 + 1 pad)

#define OTPB   1024               // o columns per phase-2 block (4/thread)
#define MSLAB  32                 // m rows per phase-2 block (small tail)

#define NP1    ((M_TOT / MT) * KSPLIT)                  // 1024 producers
#define NP2    ((OUT_F / OTPB) * (M_TOT / MSLAB))       // 1024 consumers

__device__ __align__(16) float g_tp[KSPLIT][M_TOT][RANK];    // 4 MB partials
__device__ int g_cnt[M_TOT / MT];                            // 128 counters

typedef unsigned long long u64;

__device__ __forceinline__ u64 pk2(float lo, float hi) {
    u64 r; asm("mov.b64 %0, {%1,%2};" : "=l"(r) : "f"(lo), "f"(hi)); return r;
}
__device__ __forceinline__ void fma2(u64 &d, u64 a, u64 b) {
    asm("fma.rn.f32x2 %0, %1, %2, %0;" : "+l"(d) : "l"(a), "l"(b));
}
__device__ __forceinline__ float2 up2(u64 v) {
    float2 f; asm("mov.b64 {%0,%1}, %2;" : "=f"(f.x), "=f"(f.y) : "l"(v)); return f;
}

__global__ void lora_zero() {
    g_cnt[threadIdx.x] = 0;
}

__global__ __launch_bounds__(256, 2)
void lora_all(const float* __restrict__ x,
              const float* __restrict__ A,
              const float* __restrict__ B,
              const float* __restrict__ bias,
              float* __restrict__ out)
{
    __shared__ __align__(16) char sraw[41472];

    const int bid  = blockIdx.x;
    const int tid  = threadIdx.x;
    const int lane = tid & 31;
    const int w    = tid >> 5;

    if (bid < NP1) {
        // ================= PHASE 1 (producer) =================
        float*  xs    = (float*)sraw;                  // [2][KC][XP]
        float4* as4   = (float4*)(sraw + 33280);       // [2][KC*4]
        float*  tredf = (float*)sraw;                  // reduction alias

        const int ks   = bid & (KSPLIT - 1);
        const int mt   = bid >> 3;                     // 0..127
        const int mbase = mt * MT;
        const int k0    = ks * KRANGE;

        const int lm = tid >> 3;
        const int lc = (tid & 7) * 4;
        const float* xg = x + (size_t)(mbase + lm) * IN_F + k0 + lc;

        const int ka = tid >> 2;
        const int rq = tid & 3;
        const float* Ag = A + (size_t)(4 * rq) * IN_F + k0 + ka;

        u64 acc[2][8];
        #pragma unroll
        for (int mp = 0; mp < 2; ++mp)
            #pragma unroll
            for (int rp = 0; rp < 8; ++rp) acc[mp][rp] = 0ull;

        float4 xr[2][2], ar;

        #pragma unroll
        for (int i = 0; i < 2; ++i)
            #pragma unroll
            for (int j = 0; j < 2; ++j)
                xr[i][j] = *(const float4*)(xg + (size_t)(32 * i) * IN_F + 32 * j);
        ar.x = Ag[0];
        ar.y = Ag[(size_t)1 * IN_F];
        ar.z = Ag[(size_t)2 * IN_F];
        ar.w = Ag[(size_t)3 * IN_F];

        #pragma unroll
        for (int i = 0; i < 2; ++i)
            #pragma unroll
            for (int j = 0; j < 2; ++j) {
                const int m = lm + 32 * i;
                const int c = lc + 32 * j;
                xs[(c + 0) * XP + m] = xr[i][j].x;
                xs[(c + 1) * XP + m] = xr[i][j].y;
                xs[(c + 2) * XP + m] = xr[i][j].z;
                xs[(c + 3) * XP + m] = xr[i][j].w;
            }
        as4[tid] = make_float4(2.0f * ar.x, 2.0f * ar.y, 2.0f * ar.z, 2.0f * ar.w);
        __syncthreads();

        for (int c = 0; c < NCH; ++c) {
            const int buf = c & 1;

            if (c + 1 < NCH) {
                const int kc1 = (c + 1) * KC;
                #pragma unroll
                for (int i = 0; i < 2; ++i)
                    #pragma unroll
                    for (int j = 0; j < 2; ++j)
                        xr[i][j] = *(const float4*)(xg + kc1 + (size_t)(32 * i) * IN_F + 32 * j);
                ar.x = Ag[kc1];
                ar.y = Ag[kc1 + (size_t)1 * IN_F];
                ar.z = Ag[kc1 + (size_t)2 * IN_F];
                ar.w = Ag[kc1 + (size_t)3 * IN_F];
            }

            const float*  xbc = xs + buf * (KC * XP);
            const float4* abc = as4 + buf * (KC * 4);
            #pragma unroll
            for (int kk = 0; kk < 8; ++kk) {
                const int k = w * 8 + kk;
                const float xv0 = xbc[k * XP + lane];
                const float xv1 = xbc[k * XP + 32 + lane];
                const u64 xd0 = pk2(xv0, xv0);
                const u64 xd1 = pk2(xv1, xv1);
                const ulonglong2* ap = (const ulonglong2*)(abc + k * 4);
                const ulonglong2 a01 = ap[0], a23 = ap[1];
                fma2(acc[0][0], xd0, a01.x); fma2(acc[1][0], xd1, a01.x);
                fma2(acc[0][1], xd0, a01.y); fma2(acc[1][1], xd1, a01.y);
                fma2(acc[0][2], xd0, a23.x); fma2(acc[1][2], xd1, a23.x);
                fma2(acc[0][3], xd0, a23.y); fma2(acc[1][3], xd1, a23.y);
                const ulonglong2 a45 = ap[2], a67 = ap[3];
                fma2(acc[0][4], xd0, a45.x); fma2(acc[1][4], xd1, a45.x);
                fma2(acc[0][5], xd0, a45.y); fma2(acc[1][5], xd1, a45.y);
                fma2(acc[0][6], xd0, a67.x); fma2(acc[1][6], xd1, a67.x);
                fma2(acc[0][7], xd0, a67.y); fma2(acc[1][7], xd1, a67.y);
            }

            if (c + 1 < NCH) {
                float* xb = xs + ((c + 1) & 1) * (KC * XP);
                #pragma unroll
                for (int i = 0; i < 2; ++i)
                    #pragma unroll
                    for (int j = 0; j < 2; ++j) {
                        const int m = lm + 32 * i;
                        const int cc = lc + 32 * j;
                        xb[(cc + 0) * XP + m] = xr[i][j].x;
                        xb[(cc + 1) * XP + m] = xr[i][j].y;
                        xb[(cc + 2) * XP + m] = xr[i][j].z;
                        xb[(cc + 3) * XP + m] = xr[i][j].w;
                    }
                as4[((c + 1) & 1) * 256 + tid] =
                    make_float4(2.0f * ar.x, 2.0f * ar.y, 2.0f * ar.z, 2.0f * ar.w);
            }
            __syncthreads();
        }

        // cross-warp reduction (lane-swizzled, aliases xs)
        #pragma unroll
        for (int mp = 0; mp < 2; ++mp) {
            const int m = lane + 32 * mp;
            const int base = w * 1024 + m * 16;
            #pragma unroll
            for (int rp = 0; rp < 8; ++rp) {
                const float2 f = up2(acc[mp][rp]);
                tredf[base + ((2 * rp     + lane) & 15)] = f.x;
                tredf[base + ((2 * rp + 1 + lane) & 15)] = f.y;
            }
        }
        __syncthreads();

        {
            const int m  = tid >> 2;
            const int r0 = (tid & 3) * 4;
            const int lw = m & 31;
            float s[4];
            #pragma unroll
            for (int j = 0; j < 4; ++j) {
                const int cr = (r0 + j + lw) & 15;
                float v = 0.0f;
                #pragma unroll
                for (int w8 = 0; w8 < 8; ++w8)
                    v += tredf[w8 * 1024 + m * 16 + cr];
                s[j] = v;
            }
            *(float4*)&g_tp[ks][mbase + m][r0] = make_float4(s[0], s[1], s[2], s[3]);
        }

        // release: make g_tp visible, then signal this (mt, ks) tile done
        __threadfence();
        __syncthreads();
        if (tid == 0) atomicAdd(&g_cnt[mt], 1);

    } else {
        // ================= PHASE 2 (consumer) =================
        u64* t_d = (u64*)sraw;                   // [MSLAB][RANK], 4 KB

        const int b2    = bid - NP1;             // 0..1023
        const int oblk  = b2 & 3;
        const int slab  = b2 >> 2;               // 0..255
        const int o0    = oblk * OTPB + tid * 4;
        const int m0    = slab * MSLAB;
        const int mt    = m0 / MT;               // producer tile

        // load B + bias while waiting is pending (independent of g_tp)
        u64 bu[2][RANK];
        #pragma unroll
        for (int op = 0; op < 2; ++op) {
            float Bv0[RANK], Bv1[RANK];
            #pragma unroll
            for (int q = 0; q < 4; ++q) {
                *(float4*)&Bv0[4 * q] = *(const float4*)&B[(size_t)(o0 + 2 * op)     * RANK + 4 * q];
                *(float4*)&Bv1[4 * q] = *(const float4*)&B[(size_t)(o0 + 2 * op + 1) * RANK + 4 * q];
            }
            #pragma unroll
            for (int r = 0; r < RANK; ++r)
                bu[op][r] = pk2(Bv0[r], Bv1[r]);
        }
        const float4 bi4 = *(const float4*)&bias[o0];
        const u64 bias2[2] = { pk2(bi4.x, bi4.y), pk2(bi4.z, bi4.w) };

        // acquire spin: all 8 ks-partials for this mt present
        if (tid == 0) {
            int v;
            do {
                asm volatile("ld.global.acquire.gpu.b32 %0, [%1];"
                             : "=r"(v) : "l"(&g_cnt[mt]) : "memory");
                if (v < KSPLIT) __nanosleep(200);
            } while (v < KSPLIT);
        }
        __syncthreads();
        __threadfence();

        // stage t slab: sum KSPLIT partials, store duplicated (threads 0..127)
        if (tid < MSLAB * 4) {
            const int m = tid >> 2, q = tid & 3;
            float4 s = make_float4(0, 0, 0, 0);
            #pragma unroll
            for (int sl = 0; sl < KSPLIT; ++sl) {
                const float4 v = *(const float4*)&g_tp[sl][m0 + m][4 * q];
                s.x += v.x; s.y += v.y; s.z += v.z; s.w += v.w;
            }
            t_d[m * RANK + 4 * q + 0] = pk2(s.x, s.x);
            t_d[m * RANK + 4 * q + 1] = pk2(s.y, s.y);
            t_d[m * RANK + 4 * q + 2] = pk2(s.z, s.z);
            t_d[m * RANK + 4 * q + 3] = pk2(s.w, s.w);
        }
        __syncthreads();

        // main loop: 2 m per iteration -> 4 independent FMA chains
        for (int m = 0; m < MSLAB; m += 2) {
            const ulonglong2* tp0 = (const ulonglong2*)&t_d[m * RANK];
            const ulonglong2* tp1 = (const ulonglong2*)&t_d[(m + 1) * RANK];
            u64 a0 = bias2[0], a1 = bias2[1];
            u64 b0 = bias2[0], b1 = bias2[1];
            #pragma unroll
            for (int rp = 0; rp < 8; ++rp) {
                const ulonglong2 t20 = tp0[rp];
                const ulonglong2 t21 = tp1[rp];
                fma2(a0, t20.x, bu[0][2 * rp]);
                fma2(a1, t20.x, bu[1][2 * rp]);
                fma2(b0, t21.x, bu[0][2 * rp]);
                fma2(b1, t21.x, bu[1][2 * rp]);
                fma2(a0, t20.y, bu[0][2 * rp + 1]);
                fma2(a1, t20.y, bu[1][2 * rp + 1]);
                fma2(b0, t21.y, bu[0][2 * rp + 1]);
                fma2(b1, t21.y, bu[1][2 * rp + 1]);
            }
            const float2 alo = up2(a0), ahi = up2(a1);
            const float2 blo = up2(b0), bhi = up2(b1);
            *(float4*)&out[(size_t)(m0 + m)     * OUT_F + o0] =
                make_float4(alo.x, alo.y, ahi.x, ahi.y);
            *(float4*)&out[(size_t)(m0 + m + 1) * OUT_F + o0] =
                make_float4(blo.x, blo.y, bhi.x, bhi.y);
        }
    }
}

extern "C" void kernel_launch(void* const* d_in, const int* in_sizes, int n_in,
                              void* d_out, int out_size) {
    const float* x    = (const float*)d_in[0];   // [8192, 4096]
    const float* A    = (const float*)d_in[1];   // [16, 4096]
    const float* B    = (const float*)d_in[2];   // [4096, 16]
    const float* bias = (const float*)d_in[3];   // [4096]
    float* out = (float*)d_out;                  // [8192, 4096]

    lora_zero<<<1, M_TOT / MT>>>();
    lora_all<<<NP1 + NP2, 256>>>(x, A, B, bias, out);
}

// round 17
// speedup vs baseline: 1.2907x; 1.0418x over previous
#include <cuda_runtime.h>
#include <cuda_bf16.h>
#include <cstdint>

// LoRA low-rank, 2-kernel pipeline (round 15):
//   phase1 : NO x-transpose. Thread keeps x in registers (full-line LDG);
//            A staged once per block (32 KB, broadcast-friendly layout);
//            barrier-free main loop; width-8 shfl reduction over k-lanes.
//   phase2 : R10 verbatim (B in regs, t broadcast from smem, occ 2).

#define IN_F   4096
#define OUT_F  4096
#define RANK   16
#define M_TOT  8192

#define KSPLIT 8
#define KRANGE (IN_F / KSPLIT)    // 512
#define MT     64                 // m rows per phase-1 block
#define NCHU   16                 // chunks of 32 k
#define NKQ    (KRANGE / 4)       // 128 kq (k-quads) per slice

#define OTPB   1024               // o columns per phase-2 block
#define MSLAB  128                // m rows per phase-2 block

__device__ __align__(16) float g_tp[KSPLIT][M_TOT][RANK];    // 4 MB partials

typedef unsigned long long u64;

__device__ __forceinline__ u64 pk2(float lo, float hi) {
    u64 r; asm("mov.b64 %0, {%1,%2};" : "=l"(r) : "f"(lo), "f"(hi)); return r;
}
__device__ __forceinline__ void fma2(u64 &d, u64 a, u64 b) {
    asm("fma.rn.f32x2 %0, %1, %2, %0;" : "+l"(d) : "l"(a), "l"(b));
}
__device__ __forceinline__ float2 up2(u64 v) {
    float2 f; asm("mov.b64 {%0,%1}, %2;" : "=f"(f.x), "=f"(f.y) : "l"(v)); return f;
}

// ---------------- phase 1 ----------------
// as_re layout: plane p = j*4 + rpq  (j = k mod 4, rpq = rank quad r/4)
//   as_re[p*NKQ + kq] = float4{2A[4rpq..4rpq+3][kq*4+j]}  (= 2 rank-pair u64)
// Inner LDS.128: 8 lanes read consecutive kq -> 128B, broadcast x4 -> 1 wf.
__global__ __launch_bounds__(256)
void lora_phase1(const float* __restrict__ x,
                 const float* __restrict__ A) {
    __shared__ __align__(16) float4 as_re[16 * NKQ];   // 32 KB

    const int tid  = threadIdx.x;
    const int ks   = blockIdx.x & (KSPLIT - 1);
    const int mt   = blockIdx.x >> 3;                  // 0..127
    const int mbase = mt * MT;
    const int k0    = ks * KRANGE;

    // ---- stage A slice once (coalesced reads, 2-way STS) ----
    {
        const int r  = tid >> 4;                       // 0..15
        const int kk = tid & 15;                       // 0..15
        const int p_base = (r >> 2);                   // rpq
        const int comp   = r & 3;
        #pragma unroll
        for (int it = 0; it < 8; ++it) {
            const int kq = it * 16 + kk;               // 0..127
            const float4 v = *(const float4*)&A[(size_t)r * IN_F + k0 + kq * 4];
            float* base = (float*)as_re;
            // component j of v -> plane j*4+rpq, slot kq, comp r&3
            base[((0 * 4 + p_base) * NKQ + kq) * 4 + comp] = 2.0f * v.x;
            base[((1 * 4 + p_base) * NKQ + kq) * 4 + comp] = 2.0f * v.y;
            base[((2 * 4 + p_base) * NKQ + kq) * 4 + comp] = 2.0f * v.z;
            base[((3 * 4 + p_base) * NKQ + kq) * 4 + comp] = 2.0f * v.w;
        }
    }
    __syncthreads();

    // ---- barrier-free main loop ----
    const int row = tid >> 3;                          // 0..31
    const int kqg = tid & 7;                           // kq within chunk
    const float* xg0 = x + (size_t)(mbase + row) * IN_F + k0 + kqg * 4;
    const float* xg1 = xg0 + (size_t)32 * IN_F;

    u64 acc[2][8];
    #pragma unroll
    for (int mp = 0; mp < 2; ++mp)
        #pragma unroll
        for (int rp = 0; rp < 8; ++rp) acc[mp][rp] = 0ull;

    float4 xa0 = *(const float4*)xg0;
    float4 xa1 = *(const float4*)xg1;

    for (int c = 0; c < NCHU; ++c) {
        float4 xb0, xb1;
        if (c + 1 < NCHU) {
            xb0 = *(const float4*)(xg0 + (c + 1) * 32);
            xb1 = *(const float4*)(xg1 + (c + 1) * 32);
        }

        const int kq = c * 8 + kqg;
        const float xv0[4] = { xa0.x, xa0.y, xa0.z, xa0.w };
        const float xv1[4] = { xa1.x, xa1.y, xa1.z, xa1.w };

        #pragma unroll
        for (int j = 0; j < 4; ++j) {
            const u64 xd0 = pk2(xv0[j], xv0[j]);
            const u64 xd1 = pk2(xv1[j], xv1[j]);
            const ulonglong2* ap = (const ulonglong2*)(as_re + (j * 4) * NKQ + kq);
            #pragma unroll
            for (int rpq = 0; rpq < 4; ++rpq) {
                const ulonglong2 a2 = ap[rpq * NKQ];
                fma2(acc[0][2 * rpq],     xd0, a2.x);
                fma2(acc[0][2 * rpq + 1], xd0, a2.y);
                fma2(acc[1][2 * rpq],     xd1, a2.x);
                fma2(acc[1][2 * rpq + 1], xd1, a2.y);
            }
        }

        xa0 = xb0; xa1 = xb1;
    }

    // ---- reduce across the 8 k-lanes of each row (width-8 shfl) ----
    float2 res[2][8];
    #pragma unroll
    for (int mp = 0; mp < 2; ++mp)
        #pragma unroll
        for (int rp = 0; rp < 8; ++rp) {
            float2 f = up2(acc[mp][rp]);
            #pragma unroll
            for (int off = 4; off; off >>= 1) {
                f.x += __shfl_down_sync(0xffffffffu, f.x, off, 8);
                f.y += __shfl_down_sync(0xffffffffu, f.y, off, 8);
            }
            res[mp][rp] = f;
        }

    if ((tid & 7) == 0) {
        #pragma unroll
        for (int mp = 0; mp < 2; ++mp) {
            float* dst = &g_tp[ks][mbase + row + 32 * mp][0];
            *(float4*)(dst + 0)  = make_float4(res[mp][0].x, res[mp][0].y,
                                               res[mp][1].x, res[mp][1].y);
            *(float4*)(dst + 4)  = make_float4(res[mp][2].x, res[mp][2].y,
                                               res[mp][3].x, res[mp][3].y);
            *(float4*)(dst + 8)  = make_float4(res[mp][4].x, res[mp][4].y,
                                               res[mp][5].x, res[mp][5].y);
            *(float4*)(dst + 12) = make_float4(res[mp][6].x, res[mp][6].y,
                                               res[mp][7].x, res[mp][7].y);
        }
    }
}

// ---------------- phase 2 (R10 verbatim) ----------------
__global__ __launch_bounds__(256, 2)
void lora_phase2(const float* __restrict__ B,
                 const float* __restrict__ bias,
                 float* __restrict__ out) {
    __shared__ u64 t_d[MSLAB][RANK];     // 16 KB, (t,t) duplicated

    const int tid   = threadIdx.x;
    const int oblk  = blockIdx.x & 3;
    const int mslab = blockIdx.x >> 2;
    const int o0    = oblk * OTPB + tid * 4;
    const int m0    = mslab * MSLAB;

    u64 bu[2][RANK];
    #pragma unroll
    for (int op = 0; op < 2; ++op) {
        float Bv0[RANK], Bv1[RANK];
        #pragma unroll
        for (int q = 0; q < 4; ++q) {
            *(float4*)&Bv0[4 * q] = *(const float4*)&B[(size_t)(o0 + 2 * op)     * RANK + 4 * q];
            *(float4*)&Bv1[4 * q] = *(const float4*)&B[(size_t)(o0 + 2 * op + 1) * RANK + 4 * q];
        }
        #pragma unroll
        for (int r = 0; r < RANK; ++r)
            bu[op][r] = pk2(Bv0[r], Bv1[r]);
    }
    const float4 bi4 = *(const float4*)&bias[o0];
    const u64 bias2[2] = { pk2(bi4.x, bi4.y), pk2(bi4.z, bi4.w) };

    #pragma unroll
    for (int j = 0; j < 2; ++j) {
        const int idx = tid * 2 + j;      // 0..511
        const int m = idx >> 2, q = idx & 3;
        float4 s = make_float4(0, 0, 0, 0);
        #pragma unroll
        for (int sl = 0; sl < KSPLIT; ++sl) {
            const float4 v = *(const float4*)&g_tp[sl][m0 + m][4 * q];
            s.x += v.x; s.y += v.y; s.z += v.z; s.w += v.w;
        }
        t_d[m][4 * q + 0] = pk2(s.x, s.x);
        t_d[m][4 * q + 1] = pk2(s.y, s.y);
        t_d[m][4 * q + 2] = pk2(s.z, s.z);
        t_d[m][4 * q + 3] = pk2(s.w, s.w);
    }
    __syncthreads();

    for (int m = 0; m < MSLAB; m += 2) {
        const ulonglong2* tp0 = (const ulonglong2*)&t_d[m][0];
        const ulonglong2* tp1 = (const ulonglong2*)&t_d[m + 1][0];
        u64 a0 = bias2[0], a1 = bias2[1];
        u64 b0 = bias2[0], b1 = bias2[1];
        #pragma unroll
        for (int rp = 0; rp < 8; ++rp) {
            const ulonglong2 t20 = tp0[rp];
            const ulonglong2 t21 = tp1[rp];
            fma2(a0, t20.x, bu[0][2 * rp]);
            fma2(a1, t20.x, bu[1][2 * rp]);
            fma2(b0, t21.x, bu[0][2 * rp]);
            fma2(b1, t21.x, bu[1][2 * rp]);
            fma2(a0, t20.y, bu[0][2 * rp + 1]);
            fma2(a1, t20.y, bu[1][2 * rp + 1]);
            fma2(b0, t21.y, bu[0][2 * rp + 1]);
            fma2(b1, t21.y, bu[1][2 * rp + 1]);
        }
        const float2 alo = up2(a0), ahi = up2(a1);
        const float2 blo = up2(b0), bhi = up2(b1);
        *(float4*)&out[(size_t)(m0 + m)     * OUT_F + o0] =
            make_float4(alo.x, alo.y, ahi.x, ahi.y);
        *(float4*)&out[(size_t)(m0 + m + 1) * OUT_F + o0] =
            make_float4(blo.x, blo.y, bhi.x, bhi.y);
    }
}

extern "C" void kernel_launch(void* const* d_in, const int* in_sizes, int n_in,
                              void* d_out, int out_size) {
    const float* x    = (const float*)d_in[0];   // [8192, 4096]
    const float* A    = (const float*)d_in[1];   // [16, 4096]
    const float* B    = (const float*)d_in[2];   // [4096, 16]
    const float* bias = (const float*)d_in[3];   // [4096]
    float* out = (float*)d_out;                  // [8192, 4096]

    lora_phase1<<<(M_TOT / MT) * KSPLIT, 256>>>(x, A);
    lora_phase2<<<(OUT_F / OTPB) * (M_TOT / MSLAB), 256>>>(B, bias, out);
}